// round 3
// baseline (speedup 1.0000x reference)
#include <cuda_runtime.h>
#include <math.h>

// Shapes
#define NB 8
#define NS 4096
#define ND 2048
#define NH 16
#define NDK 128
#define SCALE 0.08838834764831845f   // 1/sqrt(128)

// -------- device scratch (no allocations allowed) --------
__device__ __align__(16) float g_qbp[8 * NB * ND];          // split-K partials for qb
__device__ __align__(16) float g_qb[NB * ND];               // (query@Wq)+q_bias, [b][h*128+d]
__device__ __align__(16) float g_A[NB * NH * ND];           // A[b][h][e]
__device__ __align__(16) float g_pos[NS * NB * NH];         // qb . key_pos
__device__ __align__(16) float g_scores[NS * NB * NH];      // final scores (pre-softmax)
__device__ float g_m[NB * NH];
__device__ float g_linv[NB * NH];
__device__ __align__(16) float g_upart[8 * NB * NH * ND];   // [jc][b][h][e]
__device__ __align__(16) float g_xpart[8 * NB * ND];        // [ec][b][c]
__device__ __align__(16) float g_x[NB * ND];
__device__ __align__(16) float g_opart[8 * NB * ND];        // [gc][b][f]

// ---------------- K1: qb partials: (query @ Wq), split over g ----------------
__global__ void k_qbp(const float* __restrict__ query, const float* __restrict__ Wq) {
    int tid = threadIdx.x;
    int c   = blockIdx.x * 256 + tid;
    int g0  = blockIdx.y * 256;
    __shared__ float qs[8][256];
    for (int idx = tid; idx < 2048; idx += 256)
        qs[idx >> 8][idx & 255] = query[(idx >> 8) * ND + g0 + (idx & 255)];
    __syncthreads();
    float acc[8] = {0.f,0.f,0.f,0.f,0.f,0.f,0.f,0.f};
#pragma unroll 4
    for (int g = 0; g < 256; g++) {
        float w = Wq[(g0 + g) * ND + c];
#pragma unroll
        for (int b = 0; b < 8; b++) acc[b] = fmaf(w, qs[b][g], acc[b]);
    }
#pragma unroll
    for (int b = 0; b < 8; b++) g_qbp[(blockIdx.y * 8 + b) * ND + c] = acc[b];
}

// ---------------- K1b: reduce partials + q_bias ----------------
__global__ void k_qb(const float* __restrict__ q_bias) {
    int i = blockIdx.x * 256 + threadIdx.x;   // 16384
    int c = i & (ND - 1);
    int b = i >> 11;
    float s = q_bias[c];
#pragma unroll
    for (int gc = 0; gc < 8; gc++) s += g_qbp[(gc * 8 + b) * ND + c];
    g_qb[i] = s;
}

// ---------------- K2: A[b][h][e] = sum_d Wk[e][h*128+d] * qb[b][h*128+d] ----------------
__global__ void k_A(const float* __restrict__ Wk) {
    int tid = threadIdx.x;           // 128
    int h   = blockIdx.y;
    int e0  = blockIdx.x * 128;
    __shared__ float qbs[8][128];
    __shared__ float wks[128][65];   // 65 stride: bank-conflict-free column reads
    for (int idx = tid; idx < 1024; idx += 128)
        qbs[idx >> 7][idx & 127] = g_qb[(idx >> 7) * ND + h * NDK + (idx & 127)];
    float acc[8] = {0.f,0.f,0.f,0.f,0.f,0.f,0.f,0.f};
    for (int st = 0; st < 2; st++) {
        __syncthreads();
        for (int idx = tid; idx < 128 * 64; idx += 128) {
            int r = idx >> 6, cc = idx & 63;
            wks[r][cc] = Wk[(e0 + r) * ND + h * NDK + st * 64 + cc];
        }
        __syncthreads();
#pragma unroll 4
        for (int d = 0; d < 64; d++) {
            float w = wks[tid][d];
#pragma unroll
            for (int b = 0; b < 8; b++) acc[b] = fmaf(w, qbs[b][st * 64 + d], acc[b]);
        }
    }
    int e = e0 + tid;
#pragma unroll
    for (int b = 0; b < 8; b++) g_A[(b * NH + h) * ND + e] = acc[b];
}

// ---------------- K3: pos[j][b][h] = qb[b][h] . key_pos[j][h] ----------------
__global__ void k_pos(const float* __restrict__ key_pos) {
    int j    = blockIdx.x;
    int h    = threadIdx.x >> 5;
    int lane = threadIdx.x & 31;
    float4 kv = *(const float4*)&key_pos[(j * NH + h) * NDK + lane * 4];
    float acc[8];
#pragma unroll
    for (int b = 0; b < 8; b++) {
        float4 q4 = *(const float4*)&g_qb[b * ND + h * NDK + lane * 4];
        acc[b] = kv.x * q4.x + kv.y * q4.y + kv.z * q4.z + kv.w * q4.w;
    }
#pragma unroll
    for (int off = 16; off; off >>= 1)
#pragma unroll
        for (int b = 0; b < 8; b++)
            acc[b] += __shfl_xor_sync(0xffffffffu, acc[b], off);
    if (lane == 0) {
#pragma unroll
        for (int b = 0; b < 8; b++) g_pos[j * (NB * NH) + b * NH + h] = acc[b];
    }
}

// ---------------- K4: score pass (key stream, 16 FMA/element) ----------------
__global__ __launch_bounds__(512, 1) void k_scores(const float* __restrict__ key) {
    int b    = blockIdx.y;
    int warp = threadIdx.x >> 5;
    int lane = threadIdx.x & 31;
    int j0   = blockIdx.x * 64 + warp * 4;
    __shared__ __align__(16) float As[16 * 512];

    float acc[16][4];
#pragma unroll
    for (int h = 0; h < 16; h++)
#pragma unroll
        for (int jj = 0; jj < 4; jj++) acc[h][jj] = 0.f;

    for (int st = 0; st < 4; st++) {
        __syncthreads();
        for (int idx = threadIdx.x; idx < 2048; idx += 512) {
            int h = idx >> 7, el4 = idx & 127;
            ((float4*)As)[idx] = *(const float4*)&g_A[(b * NH + h) * ND + st * 512 + el4 * 4];
        }
        __syncthreads();
#pragma unroll
        for (int it = 0; it < 4; it++) {
            int eb = st * 512 + it * 128 + lane * 4;
            float4 kv[4];
#pragma unroll
            for (int jj = 0; jj < 4; jj++)
                kv[jj] = *(const float4*)&key[((j0 + jj) * NB + b) * ND + eb];
#pragma unroll
            for (int h = 0; h < 16; h++) {
                float4 a = *(const float4*)&As[h * 512 + it * 128 + lane * 4];
#pragma unroll
                for (int jj = 0; jj < 4; jj++) {
                    acc[h][jj] = fmaf(a.x, kv[jj].x, acc[h][jj]);
                    acc[h][jj] = fmaf(a.y, kv[jj].y, acc[h][jj]);
                    acc[h][jj] = fmaf(a.z, kv[jj].z, acc[h][jj]);
                    acc[h][jj] = fmaf(a.w, kv[jj].w, acc[h][jj]);
                }
            }
        }
    }
#pragma unroll
    for (int off = 16; off; off >>= 1)
#pragma unroll
        for (int h = 0; h < 16; h++)
#pragma unroll
            for (int jj = 0; jj < 4; jj++)
                acc[h][jj] += __shfl_xor_sync(0xffffffffu, acc[h][jj], off);

    if (lane == 0) {
#pragma unroll
        for (int jj = 0; jj < 4; jj++) {
            int j = j0 + jj;
#pragma unroll
            for (int h = 0; h < 16; h++)
                g_scores[j * 128 + b * 16 + h] =
                    (acc[h][jj] + g_pos[j * 128 + b * 16 + h]) * SCALE;
        }
    }
}

// ---------------- K5: softmax stats per (b,h) ----------------
__global__ void k_softmax() {
    int bh = blockIdx.x;
    int tid = threadIdx.x;
    __shared__ float red[256];
    float mx = -1e30f;
    for (int j = tid; j < NS; j += 256)
        mx = fmaxf(mx, g_scores[j * (NB * NH) + bh]);
    red[tid] = mx; __syncthreads();
    for (int s = 128; s; s >>= 1) { if (tid < s) red[tid] = fmaxf(red[tid], red[tid + s]); __syncthreads(); }
    float m = red[0]; __syncthreads();
    float sum = 0.f;
    for (int j = tid; j < NS; j += 256)
        sum += __expf(g_scores[j * (NB * NH) + bh] - m);
    red[tid] = sum; __syncthreads();
    for (int s = 128; s; s >>= 1) { if (tid < s) red[tid] += red[tid + s]; __syncthreads(); }
    if (tid == 0) { g_m[bh] = m; g_linv[bh] = 1.0f / red[0]; }
}

// ---------------- K6: value pass -> u partials ----------------
__global__ void k_value(const float* __restrict__ value) {
    int tid = threadIdx.x;                  // 256
    int b = blockIdx.y, jc = blockIdx.z;
    int e = blockIdx.x * 256 + tid;
    int j0 = jc * 512;
    __shared__ __align__(16) float ws[512 * 16];
    __shared__ float ms[16], ls[16];
    if (tid < 16) { ms[tid] = g_m[b * 16 + tid]; ls[tid] = g_linv[b * 16 + tid]; }
    __syncthreads();
    for (int idx = tid; idx < 8192; idx += 256) {
        int jl = idx >> 4, h = idx & 15;
        ws[idx] = __expf(g_scores[(j0 + jl) * 128 + b * 16 + h] - ms[h]) * ls[h];
    }
    __syncthreads();
    float acc[16];
#pragma unroll
    for (int h = 0; h < 16; h++) acc[h] = 0.f;
    const float* vp = value + ((size_t)j0 * NB + b) * ND + e;
#pragma unroll 4
    for (int jl = 0; jl < 512; jl++) {
        float val = vp[(size_t)jl * NB * ND];
        const float4* wr = (const float4*)&ws[jl * 16];
        float4 w0 = wr[0], w1 = wr[1], w2 = wr[2], w3 = wr[3];
        acc[0]  = fmaf(w0.x, val, acc[0]);  acc[1]  = fmaf(w0.y, val, acc[1]);
        acc[2]  = fmaf(w0.z, val, acc[2]);  acc[3]  = fmaf(w0.w, val, acc[3]);
        acc[4]  = fmaf(w1.x, val, acc[4]);  acc[5]  = fmaf(w1.y, val, acc[5]);
        acc[6]  = fmaf(w1.z, val, acc[6]);  acc[7]  = fmaf(w1.w, val, acc[7]);
        acc[8]  = fmaf(w2.x, val, acc[8]);  acc[9]  = fmaf(w2.y, val, acc[9]);
        acc[10] = fmaf(w2.z, val, acc[10]); acc[11] = fmaf(w2.w, val, acc[11]);
        acc[12] = fmaf(w3.x, val, acc[12]); acc[13] = fmaf(w3.y, val, acc[13]);
        acc[14] = fmaf(w3.z, val, acc[14]); acc[15] = fmaf(w3.w, val, acc[15]);
    }
#pragma unroll
    for (int h = 0; h < 16; h++)
        g_upart[((jc * 8 + b) * 16 + h) * ND + e] = acc[h];
}

// ---------------- K7: x partials = u @ Wv (per head), split over e ----------------
__global__ void k_projv(const float* __restrict__ Wv) {
    int tid = threadIdx.x;   // 128 (= d)
    int h = blockIdx.y;
    int e0 = blockIdx.x * 256;
    __shared__ float us[8][256];
    for (int idx = tid; idx < 2048; idx += 128) {
        int bb = idx >> 8, el = idx & 255;
        float s = 0.f;
#pragma unroll
        for (int jc = 0; jc < 8; jc++)
            s += g_upart[((jc * 8 + bb) * 16 + h) * ND + e0 + el];
        us[bb][el] = s;
    }
    __syncthreads();
    float acc[8] = {0.f,0.f,0.f,0.f,0.f,0.f,0.f,0.f};
#pragma unroll 4
    for (int el = 0; el < 256; el++) {
        float w = Wv[(e0 + el) * ND + h * NDK + tid];
#pragma unroll
        for (int bb = 0; bb < 8; bb++) acc[bb] = fmaf(w, us[bb][el], acc[bb]);
    }
#pragma unroll
    for (int bb = 0; bb < 8; bb++)
        g_xpart[(blockIdx.x * 8 + bb) * ND + h * NDK + tid] = acc[bb];
}

// ---------------- K7b: reduce x partials + bv ----------------
__global__ void k_xred(const float* __restrict__ bv) {
    int i = blockIdx.x * 256 + threadIdx.x;
    int c = i & (ND - 1), b = i >> 11;
    float s = bv[c];
#pragma unroll
    for (int ec = 0; ec < 8; ec++) s += g_xpart[(ec * 8 + b) * ND + c];
    g_x[i] = s;
}

// ---------------- K8: out partials = x @ Wo, split over g ----------------
__global__ void k_out(const float* __restrict__ Wo) {
    int tid = threadIdx.x;
    int f = blockIdx.x * 256 + tid;
    int g0 = blockIdx.y * 256;
    __shared__ float xs[8][256];
    for (int idx = tid; idx < 2048; idx += 256)
        xs[idx >> 8][idx & 255] = g_x[(idx >> 8) * ND + g0 + (idx & 255)];
    __syncthreads();
    float acc[8] = {0.f,0.f,0.f,0.f,0.f,0.f,0.f,0.f};
#pragma unroll 4
    for (int g = 0; g < 256; g++) {
        float w = Wo[(g0 + g) * ND + f];
#pragma unroll
        for (int b = 0; b < 8; b++) acc[b] = fmaf(w, xs[b][g], acc[b]);
    }
#pragma unroll
    for (int b = 0; b < 8; b++) g_opart[(blockIdx.y * 8 + b) * ND + f] = acc[b];
}

// ---------------- K8b: reduce out partials + bo -> d_out ----------------
__global__ void k_ored(const float* __restrict__ bo, float* __restrict__ out) {
    int i = blockIdx.x * 256 + threadIdx.x;
    int c = i & (ND - 1), b = i >> 11;
    float s = bo[c];
#pragma unroll
    for (int gc = 0; gc < 8; gc++) s += g_opart[(gc * 8 + b) * ND + c];
    out[i] = s;
}

extern "C" void kernel_launch(void* const* d_in, const int* in_sizes, int n_in,
                              void* d_out, int out_size) {
    const float* query   = (const float*)d_in[0];
    const float* key     = (const float*)d_in[1];
    const float* value   = (const float*)d_in[2];
    const float* Wq      = (const float*)d_in[3];
    const float* Wk      = (const float*)d_in[4];
    const float* Wv      = (const float*)d_in[5];
    const float* bv      = (const float*)d_in[6];
    const float* Wo      = (const float*)d_in[7];
    const float* bo      = (const float*)d_in[8];
    const float* key_pos = (const float*)d_in[9];
    const float* q_bias  = (const float*)d_in[10];
    float* out = (float*)d_out;

    k_qbp    <<<dim3(8, 8),      256>>>(query, Wq);
    k_qb     <<<64,              256>>>(q_bias);
    k_A      <<<dim3(16, 16),    128>>>(Wk);
    k_pos    <<<4096,            512>>>(key_pos);
    k_scores <<<dim3(64, 8),     512>>>(key);
    k_softmax<<<128,             256>>>();
    k_value  <<<dim3(8, 8, 8),   256>>>(value);
    k_projv  <<<dim3(8, 16),     128>>>(Wv);
    k_xred   <<<64,              256>>>(bv);
    k_out    <<<dim3(8, 8),      256>>>(Wo);
    k_ored   <<<64,              256>>>(bo, out);
}

// round 4
// speedup vs baseline: 1.0090x; 1.0090x over previous
#include <cuda_runtime.h>
#include <math.h>

// Shapes
#define NB 8
#define NS 4096
#define ND 2048
#define NH 16
#define NDK 128
#define SCALE 0.08838834764831845f   // 1/sqrt(128)

typedef unsigned long long u64;

__device__ __forceinline__ void ffma2(u64& d, u64 a, u64 b) {
    asm("fma.rn.f32x2 %0, %1, %2, %0;" : "+l"(d) : "l"(a), "l"(b));
}
__device__ __forceinline__ u64 pack2(float x, float y) {
    u64 r; asm("mov.b64 %0, {%1, %2};" : "=l"(r) : "f"(x), "f"(y)); return r;
}
__device__ __forceinline__ float2 unpack2(u64 v) {
    float2 r; asm("mov.b64 {%0, %1}, %2;" : "=f"(r.x), "=f"(r.y) : "l"(v)); return r;
}

// -------- device scratch (no allocations allowed) --------
__device__ __align__(16) float g_qbp[8 * NB * ND];
__device__ __align__(16) float g_qb[NB * ND];                 // [b][h*128+d]
__device__ __align__(16) float g_A[NB * NH * ND];             // A[b][h][e]
__device__ __align__(16) float g_pos[NS * NB * NH];
__device__ __align__(16) float g_scores[NS * NB * NH];
__device__ float g_m[NB * NH];
__device__ float g_linv[NB * NH];
__device__ __align__(16) float g_upart[16 * NB * NH * ND];    // [jc(16)][b][h][e]
__device__ __align__(16) float g_xpart[8 * NB * ND];
__device__ __align__(16) float g_x[NB * ND];
__device__ __align__(16) float g_opart[8 * NB * ND];

// ---------------- K1: qb partials: (query @ Wq), split over g ----------------
__global__ void k_qbp(const float* __restrict__ query, const float* __restrict__ Wq) {
    int tid = threadIdx.x;
    int c   = blockIdx.x * 256 + tid;
    int g0  = blockIdx.y * 256;
    __shared__ float qs[8][256];
    for (int idx = tid; idx < 2048; idx += 256)
        qs[idx >> 8][idx & 255] = query[(idx >> 8) * ND + g0 + (idx & 255)];
    __syncthreads();
    float acc[8] = {0.f,0.f,0.f,0.f,0.f,0.f,0.f,0.f};
#pragma unroll 4
    for (int g = 0; g < 256; g++) {
        float w = Wq[(g0 + g) * ND + c];
#pragma unroll
        for (int b = 0; b < 8; b++) acc[b] = fmaf(w, qs[b][g], acc[b]);
    }
#pragma unroll
    for (int b = 0; b < 8; b++) g_qbp[(blockIdx.y * 8 + b) * ND + c] = acc[b];
}

__global__ void k_qb(const float* __restrict__ q_bias) {
    int i = blockIdx.x * 256 + threadIdx.x;
    int c = i & (ND - 1);
    int b = i >> 11;
    float s = q_bias[c];
#pragma unroll
    for (int gc = 0; gc < 8; gc++) s += g_qbp[(gc * 8 + b) * ND + c];
    g_qb[i] = s;
}

// ---------------- K2: A[b][h][e] = sum_d Wk[e][h*128+d] * qb[b][h*128+d] ----------------
__global__ void k_A(const float* __restrict__ Wk) {
    int tid = threadIdx.x;           // 128
    int h   = blockIdx.y;
    int e0  = blockIdx.x * 128;
    __shared__ float qbs[8][128];
    __shared__ float wks[128][65];
    for (int idx = tid; idx < 1024; idx += 128)
        qbs[idx >> 7][idx & 127] = g_qb[(idx >> 7) * ND + h * NDK + (idx & 127)];
    float acc[8] = {0.f,0.f,0.f,0.f,0.f,0.f,0.f,0.f};
    for (int st = 0; st < 2; st++) {
        __syncthreads();
        for (int idx = tid; idx < 128 * 64; idx += 128) {
            int r = idx >> 6, cc = idx & 63;
            wks[r][cc] = Wk[(e0 + r) * ND + h * NDK + st * 64 + cc];
        }
        __syncthreads();
#pragma unroll 4
        for (int d = 0; d < 64; d++) {
            float w = wks[tid][d];
#pragma unroll
            for (int b = 0; b < 8; b++) acc[b] = fmaf(w, qbs[b][st * 64 + d], acc[b]);
        }
    }
    int e = e0 + tid;
#pragma unroll
    for (int b = 0; b < 8; b++) g_A[(b * NH + h) * ND + e] = acc[b];
}

// ---------------- K3: pos[j][b][h] = qb[b][h] . key_pos[j][h] ----------------
// warp = (h, 4 j); qb slice held in registers; merge-tree reduction (32 vals)
__global__ __launch_bounds__(256) void k_pos(const float* __restrict__ key_pos) {
    const int warp = threadIdx.x >> 5, lane = threadIdx.x & 31;
    const int h  = blockIdx.y * 8 + warp;
    const int j0 = blockIdx.x * 4;

    u64 qb[8][2];
#pragma unroll
    for (int bb = 0; bb < 8; bb++) {
        ulonglong2 q = *(const ulonglong2*)&g_qb[bb * ND + h * NDK + lane * 4];
        qb[bb][0] = q.x; qb[bb][1] = q.y;
    }
    u64 acc[4][8];
#pragma unroll
    for (int jj = 0; jj < 4; jj++)
#pragma unroll
        for (int bb = 0; bb < 8; bb++) acc[jj][bb] = 0ull;

#pragma unroll
    for (int jj = 0; jj < 4; jj++) {
        ulonglong2 kp = *(const ulonglong2*)&key_pos[((size_t)(j0 + jj) * NH + h) * NDK + lane * 4];
#pragma unroll
        for (int bb = 0; bb < 8; bb++) {
            ffma2(acc[jj][bb], qb[bb][0], kp.x);
            ffma2(acc[jj][bb], qb[bb][1], kp.y);
        }
    }
    float v[32];
#pragma unroll
    for (int jj = 0; jj < 4; jj++)
#pragma unroll
        for (int bb = 0; bb < 8; bb++) {
            float2 p = unpack2(acc[jj][bb]);
            v[jj * 8 + bb] = p.x + p.y;
        }
    // merge-tree: 32 values -> value index == lane
    int n = 32;
#pragma unroll
    for (int half = 16; half >= 1; half >>= 1) {
        int m = n >> 1;
        bool upper = (lane & half) != 0;
#pragma unroll
        for (int i = 0; i < 16; i++) {
            if (i >= m) break;
            float send = upper ? v[i] : v[i + m];
            float recv = __shfl_xor_sync(0xffffffffu, send, half);
            v[i] = (upper ? v[i + m] : v[i]) + recv;
        }
        n = m;
    }
    int jj = lane >> 3, bb = lane & 7;
    g_pos[(j0 + jj) * 128 + bb * 16 + h] = v[0];
}

// ---------------- K4: score pass — register-tiled 4j x 16h, f32x2 ----------------
__global__ __launch_bounds__(256, 1) void k_scores(const float* __restrict__ key) {
    const int b = blockIdx.y;
    const int warp = threadIdx.x >> 5, lane = threadIdx.x & 31;
    const int j0w = blockIdx.x * 32 + warp * 4;
    __shared__ __align__(16) float As[16 * 2048];
    for (int idx = threadIdx.x; idx < 8192; idx += 256)
        ((float4*)As)[idx] = ((const float4*)(g_A + (size_t)b * NH * ND))[idx];
    __syncthreads();

    u64 acc[16][4];
#pragma unroll
    for (int h = 0; h < 16; h++)
#pragma unroll
        for (int jj = 0; jj < 4; jj++) acc[h][jj] = 0ull;

    const float* kbase = key + ((size_t)j0w * NB + b) * ND + lane * 4;
#pragma unroll 2
    for (int e0 = 0; e0 < 2048; e0 += 128) {
        ulonglong2 kv[4];
#pragma unroll
        for (int jj = 0; jj < 4; jj++)
            kv[jj] = *(const ulonglong2*)(kbase + (size_t)jj * (NB * ND) + e0);
        const float* ap = As + e0 + lane * 4;
#pragma unroll
        for (int h = 0; h < 16; h++) {
            ulonglong2 a = *(const ulonglong2*)(ap + h * 2048);
#pragma unroll
            for (int jj = 0; jj < 4; jj++) {
                ffma2(acc[h][jj], a.x, kv[jj].x);
                ffma2(acc[h][jj], a.y, kv[jj].y);
            }
        }
    }
    // fold e-parity halves; value index i = jj*16 + h  (64 values)
    float v[64];
#pragma unroll
    for (int h = 0; h < 16; h++)
#pragma unroll
        for (int jj = 0; jj < 4; jj++) {
            float2 p = unpack2(acc[h][jj]);
            v[jj * 16 + h] = p.x + p.y;
        }
    // merge-tree: 64 values over 32 lanes -> lane ends with indices 2*lane, 2*lane+1
    int n = 64;
#pragma unroll
    for (int half = 16; half >= 1; half >>= 1) {
        int m = n >> 1;
        bool upper = (lane & half) != 0;
#pragma unroll
        for (int i = 0; i < 32; i++) {
            if (i >= m) break;
            float send = upper ? v[i] : v[i + m];
            float recv = __shfl_xor_sync(0xffffffffu, send, half);
            v[i] = (upper ? v[i + m] : v[i]) + recv;
        }
        n = m;
    }
#pragma unroll
    for (int k = 0; k < 2; k++) {
        int idx = lane * 2 + k;
        int jj = idx >> 4, h = idx & 15;
        int j = j0w + jj;
        g_scores[j * 128 + b * 16 + h] = (v[k] + g_pos[j * 128 + b * 16 + h]) * SCALE;
    }
}

// ---------------- K5: softmax stats per (b,h) ----------------
__global__ void k_softmax() {
    int bh = blockIdx.x;
    int tid = threadIdx.x;
    __shared__ float red[256];
    float mx = -1e30f;
    for (int j = tid; j < NS; j += 256)
        mx = fmaxf(mx, g_scores[j * (NB * NH) + bh]);
    red[tid] = mx; __syncthreads();
    for (int s = 128; s; s >>= 1) { if (tid < s) red[tid] = fmaxf(red[tid], red[tid + s]); __syncthreads(); }
    float m = red[0]; __syncthreads();
    float sum = 0.f;
    for (int j = tid; j < NS; j += 256)
        sum += __expf(g_scores[j * (NB * NH) + bh] - m);
    red[tid] = sum; __syncthreads();
    for (int s = 128; s; s >>= 1) { if (tid < s) red[tid] += red[tid + s]; __syncthreads(); }
    if (tid == 0) { g_m[bh] = m; g_linv[bh] = 1.0f / red[0]; }
}

// ---------------- K6: value pass — f32x2, 2 e-columns per thread ----------------
__global__ __launch_bounds__(256) void k_value(const float* __restrict__ value) {
    const int tid = threadIdx.x;
    const int b = blockIdx.y, jc = blockIdx.z;
    const int e = blockIdx.x * 512 + tid;       // columns e and e+256
    const int j0 = jc * 256;
    __shared__ __align__(16) float ws[256 * 16];
    __shared__ float ms[16], ls[16];
    if (tid < 16) { ms[tid] = g_m[b * 16 + tid]; ls[tid] = g_linv[b * 16 + tid]; }
    __syncthreads();
    for (int idx = tid; idx < 4096; idx += 256) {
        int jl = idx >> 4, h = idx & 15;
        ws[idx] = __expf(g_scores[(j0 + jl) * 128 + b * 16 + h] - ms[h]) * ls[h];
    }
    __syncthreads();

    u64 accA[8], accB[8];
#pragma unroll
    for (int p = 0; p < 8; p++) { accA[p] = 0ull; accB[p] = 0ull; }

    const float* vp = value + ((size_t)j0 * NB + b) * ND + e;
#pragma unroll 4
    for (int jl = 0; jl < 256; jl++) {
        float c0 = vp[0];
        float c1 = vp[256];
        vp += (size_t)NB * ND;
        u64 p0 = pack2(c0, c0), p1 = pack2(c1, c1);
        const ulonglong2* wr = (const ulonglong2*)(ws + jl * 16);
        ulonglong2 wA = wr[0], wB = wr[1];
        ffma2(accA[0], wA.x, p0); ffma2(accB[0], wA.x, p1);
        ffma2(accA[1], wA.y, p0); ffma2(accB[1], wA.y, p1);
        ffma2(accA[2], wB.x, p0); ffma2(accB[2], wB.x, p1);
        ffma2(accA[3], wB.y, p0); ffma2(accB[3], wB.y, p1);
        ulonglong2 wC = wr[2], wD = wr[3];
        ffma2(accA[4], wC.x, p0); ffma2(accB[4], wC.x, p1);
        ffma2(accA[5], wC.y, p0); ffma2(accB[5], wC.y, p1);
        ffma2(accA[6], wD.x, p0); ffma2(accB[6], wD.x, p1);
        ffma2(accA[7], wD.y, p0); ffma2(accB[7], wD.y, p1);
    }
    int rb = (jc * 8 + b) * 16;
#pragma unroll
    for (int p = 0; p < 8; p++) {
        float2 a = unpack2(accA[p]);
        float2 c = unpack2(accB[p]);
        g_upart[(rb + 2 * p    ) * ND + e]       = a.x;
        g_upart[(rb + 2 * p + 1) * ND + e]       = a.y;
        g_upart[(rb + 2 * p    ) * ND + e + 256] = c.x;
        g_upart[(rb + 2 * p + 1) * ND + e + 256] = c.y;
    }
}

// ---------------- K7: x partials = u @ Wv (per head), split over e ----------------
__global__ void k_projv(const float* __restrict__ Wv) {
    int tid = threadIdx.x;   // 128 (= d)
    int h = blockIdx.y;
    int e0 = blockIdx.x * 256;
    __shared__ float us[8][256];
    for (int idx = tid; idx < 2048; idx += 128) {
        int bb = idx >> 8, el = idx & 255;
        float s = 0.f;
#pragma unroll
        for (int jc = 0; jc < 16; jc++)
            s += g_upart[((jc * 8 + bb) * 16 + h) * ND + e0 + el];
        us[bb][el] = s;
    }
    __syncthreads();
    float acc[8] = {0.f,0.f,0.f,0.f,0.f,0.f,0.f,0.f};
#pragma unroll 4
    for (int el = 0; el < 256; el++) {
        float w = Wv[(e0 + el) * ND + h * NDK + tid];
#pragma unroll
        for (int bb = 0; bb < 8; bb++) acc[bb] = fmaf(w, us[bb][el], acc[bb]);
    }
#pragma unroll
    for (int bb = 0; bb < 8; bb++)
        g_xpart[(blockIdx.x * 8 + bb) * ND + h * NDK + tid] = acc[bb];
}

__global__ void k_xred(const float* __restrict__ bv) {
    int i = blockIdx.x * 256 + threadIdx.x;
    int c = i & (ND - 1), b = i >> 11;
    float s = bv[c];
#pragma unroll
    for (int ec = 0; ec < 8; ec++) s += g_xpart[(ec * 8 + b) * ND + c];
    g_x[i] = s;
}

// ---------------- K8: out partials = x @ Wo, split over g ----------------
__global__ void k_out(const float* __restrict__ Wo) {
    int tid = threadIdx.x;
    int f = blockIdx.x * 256 + tid;
    int g0 = blockIdx.y * 256;
    __shared__ float xs[8][256];
    for (int idx = tid; idx < 2048; idx += 256)
        xs[idx >> 8][idx & 255] = g_x[(idx >> 8) * ND + g0 + (idx & 255)];
    __syncthreads();
    float acc[8] = {0.f,0.f,0.f,0.f,0.f,0.f,0.f,0.f};
#pragma unroll 4
    for (int g = 0; g < 256; g++) {
        float w = Wo[(g0 + g) * ND + f];
#pragma unroll
        for (int b = 0; b < 8; b++) acc[b] = fmaf(w, xs[b][g], acc[b]);
    }
#pragma unroll
    for (int b = 0; b < 8; b++) g_opart[(blockIdx.y * 8 + b) * ND + f] = acc[b];
}

__global__ void k_ored(const float* __restrict__ bo, float* __restrict__ out) {
    int i = blockIdx.x * 256 + threadIdx.x;
    int c = i & (ND - 1), b = i >> 11;
    float s = bo[c];
#pragma unroll
    for (int gc = 0; gc < 8; gc++) s += g_opart[(gc * 8 + b) * ND + c];
    out[i] = s;
}

extern "C" void kernel_launch(void* const* d_in, const int* in_sizes, int n_in,
                              void* d_out, int out_size) {
    const float* query   = (const float*)d_in[0];
    const float* key     = (const float*)d_in[1];
    const float* value   = (const float*)d_in[2];
    const float* Wq      = (const float*)d_in[3];
    const float* Wk      = (const float*)d_in[4];
    const float* Wv      = (const float*)d_in[5];
    const float* bv      = (const float*)d_in[6];
    const float* Wo      = (const float*)d_in[7];
    const float* bo      = (const float*)d_in[8];
    const float* key_pos = (const float*)d_in[9];
    const float* q_bias  = (const float*)d_in[10];
    float* out = (float*)d_out;

    k_qbp    <<<dim3(8, 8),      256>>>(query, Wq);
    k_qb     <<<64,              256>>>(q_bias);
    k_A      <<<dim3(16, 16),    128>>>(Wk);
    k_pos    <<<dim3(1024, 2),   256>>>(key_pos);
    k_scores <<<dim3(128, 8),    256>>>(key);
    k_softmax<<<128,             256>>>();
    k_value  <<<dim3(4, 8, 16),  256>>>(value);
    k_projv  <<<dim3(8, 16),     128>>>(Wv);
    k_xred   <<<64,              256>>>(bv);
    k_out    <<<dim3(8, 8),      256>>>(Wo);
    k_ored   <<<64,              256>>>(bo, out);
}

// round 5
// speedup vs baseline: 1.1892x; 1.1785x over previous
#include <cuda_runtime.h>
#include <math.h>

// Shapes
#define NB 8
#define NS 4096
#define ND 2048
#define NH 16
#define NDK 128
#define SCALE 0.08838834764831845f   // 1/sqrt(128)

typedef unsigned long long u64;

__device__ __forceinline__ void ffma2(u64& d, u64 a, u64 b) {
    asm("fma.rn.f32x2 %0, %1, %2, %0;" : "+l"(d) : "l"(a), "l"(b));
}
__device__ __forceinline__ u64 pack2(float x, float y) {
    u64 r; asm("mov.b64 %0, {%1, %2};" : "=l"(r) : "f"(x), "f"(y)); return r;
}
__device__ __forceinline__ float2 unpack2(u64 v) {
    float2 r; asm("mov.b64 {%0, %1}, %2;" : "=f"(r.x), "=f"(r.y) : "l"(v)); return r;
}

// -------- device scratch (no allocations allowed) --------
__device__ __align__(16) float g_qbp[16 * NB * ND];           // 16 g-split partials
__device__ __align__(16) float g_qb[NB * ND];                 // [b][h*128+d]
__device__ __align__(16) float g_A[NB * NH * ND];             // A[b][h][e]
__device__ __align__(16) float g_pos[NS * NB * NH];           // SCALE * (qb . key_pos)
__device__ __align__(16) float g_scores[NS * NB * NH];        // SCALE * (A . key), no pos
__device__ float g_m[NB * NH];
__device__ float g_linv[NB * NH];
__device__ __align__(16) float g_upart[16 * NB * NH * ND];    // [jc(16)][b][h][e]
__device__ __align__(16) float g_xpart[16 * NB * ND];         // 16 e-split partials
__device__ __align__(16) float g_x[NB * ND];
__device__ __align__(16) float g_opart[16 * NB * ND];         // 16 g-split partials

// ---------------- K1: qb partials: (query @ Wq), g-split 16, MLP 8 ----------------
__global__ __launch_bounds__(256) void k_qbp(const float* __restrict__ query,
                                             const float* __restrict__ Wq) {
    int tid = threadIdx.x;
    int c   = blockIdx.x * 256 + tid;
    int g0  = blockIdx.y * 128;
    __shared__ float qs[8][128];
    for (int idx = tid; idx < 1024; idx += 256)
        qs[idx >> 7][idx & 127] = query[(idx >> 7) * ND + g0 + (idx & 127)];
    __syncthreads();
    float acc[8] = {0.f,0.f,0.f,0.f,0.f,0.f,0.f,0.f};
    for (int g = 0; g < 128; g += 8) {
        float w[8];
#pragma unroll
        for (int k2 = 0; k2 < 8; k2++) w[k2] = Wq[(g0 + g + k2) * ND + c];
#pragma unroll
        for (int k2 = 0; k2 < 8; k2++)
#pragma unroll
            for (int b = 0; b < 8; b++) acc[b] = fmaf(w[k2], qs[b][g + k2], acc[b]);
    }
#pragma unroll
    for (int b = 0; b < 8; b++) g_qbp[(blockIdx.y * 8 + b) * ND + c] = acc[b];
}

__global__ void k_qb(const float* __restrict__ q_bias) {
    int i = blockIdx.x * 256 + threadIdx.x;
    int c = i & (ND - 1);
    int b = i >> 11;
    float s = q_bias[c];
#pragma unroll
    for (int gc = 0; gc < 16; gc++) s += g_qbp[(gc * 8 + b) * ND + c];
    g_qb[i] = s;
}

// ---------------- K2: A[b][h][e] = sum_d Wk[e][h*128+d] * qb[b][h*128+d] ----------------
__global__ void k_A(const float* __restrict__ Wk) {
    int tid = threadIdx.x;           // 128
    int h   = blockIdx.y;
    int e0  = blockIdx.x * 128;
    __shared__ float qbs[8][128];
    __shared__ float wks[128][65];
    for (int idx = tid; idx < 1024; idx += 128)
        qbs[idx >> 7][idx & 127] = g_qb[(idx >> 7) * ND + h * NDK + (idx & 127)];
    float acc[8] = {0.f,0.f,0.f,0.f,0.f,0.f,0.f,0.f};
    for (int st = 0; st < 2; st++) {
        __syncthreads();
        for (int idx = tid; idx < 128 * 64; idx += 128) {
            int r = idx >> 6, cc = idx & 63;
            wks[r][cc] = Wk[(e0 + r) * ND + h * NDK + st * 64 + cc];
        }
        __syncthreads();
#pragma unroll 8
        for (int d = 0; d < 64; d++) {
            float w = wks[tid][d];
#pragma unroll
            for (int b = 0; b < 8; b++) acc[b] = fmaf(w, qbs[b][st * 64 + d], acc[b]);
        }
    }
    int e = e0 + tid;
#pragma unroll
    for (int b = 0; b < 8; b++) g_A[(b * NH + h) * ND + e] = acc[b];
}

// ---------------- K4: score pass — register-tiled 4j x 16h, f32x2 (no pos) ----------------
__global__ __launch_bounds__(256, 1) void k_scores(const float* __restrict__ key) {
    const int b = blockIdx.y;
    const int warp = threadIdx.x >> 5, lane = threadIdx.x & 31;
    const int j0w = blockIdx.x * 32 + warp * 4;
    __shared__ __align__(16) float As[16 * 2048];
    for (int idx = threadIdx.x; idx < 8192; idx += 256)
        ((float4*)As)[idx] = ((const float4*)(g_A + (size_t)b * NH * ND))[idx];
    __syncthreads();

    u64 acc[16][4];
#pragma unroll
    for (int h = 0; h < 16; h++)
#pragma unroll
        for (int jj = 0; jj < 4; jj++) acc[h][jj] = 0ull;

    const float* kbase = key + ((size_t)j0w * NB + b) * ND + lane * 4;
#pragma unroll 2
    for (int e0 = 0; e0 < 2048; e0 += 128) {
        ulonglong2 kv[4];
#pragma unroll
        for (int jj = 0; jj < 4; jj++)
            kv[jj] = *(const ulonglong2*)(kbase + (size_t)jj * (NB * ND) + e0);
        const float* ap = As + e0 + lane * 4;
#pragma unroll
        for (int h = 0; h < 16; h++) {
            ulonglong2 a = *(const ulonglong2*)(ap + h * 2048);
#pragma unroll
            for (int jj = 0; jj < 4; jj++) {
                ffma2(acc[h][jj], a.x, kv[jj].x);
                ffma2(acc[h][jj], a.y, kv[jj].y);
            }
        }
    }
    float v[64];
#pragma unroll
    for (int h = 0; h < 16; h++)
#pragma unroll
        for (int jj = 0; jj < 4; jj++) {
            float2 p = unpack2(acc[h][jj]);
            v[jj * 16 + h] = p.x + p.y;
        }
    int n = 64;
#pragma unroll
    for (int half = 16; half >= 1; half >>= 1) {
        int m = n >> 1;
        bool upper = (lane & half) != 0;
#pragma unroll
        for (int i = 0; i < 32; i++) {
            if (i >= m) break;
            float send = upper ? v[i] : v[i + m];
            float recv = __shfl_xor_sync(0xffffffffu, send, half);
            v[i] = (upper ? v[i + m] : v[i]) + recv;
        }
        n = m;
    }
#pragma unroll
    for (int k = 0; k < 2; k++) {
        int idx = lane * 2 + k;
        int jj = idx >> 4, h = idx & 15;
        int j = j0w + jj;
        g_scores[j * 128 + b * 16 + h] = v[k] * SCALE;
    }
}

// ---------------- K3: pos[j][b][h] = SCALE * (qb[b][h] . key_pos[j][h]) ----------------
__global__ __launch_bounds__(256) void k_pos(const float* __restrict__ key_pos) {
    const int warp = threadIdx.x >> 5, lane = threadIdx.x & 31;
    const int h  = blockIdx.y * 8 + warp;
    const int j0 = blockIdx.x * 4;

    u64 qb[8][2];
#pragma unroll
    for (int bb = 0; bb < 8; bb++) {
        ulonglong2 q = *(const ulonglong2*)&g_qb[bb * ND + h * NDK + lane * 4];
        qb[bb][0] = q.x; qb[bb][1] = q.y;
    }
    u64 acc[4][8];
#pragma unroll
    for (int jj = 0; jj < 4; jj++)
#pragma unroll
        for (int bb = 0; bb < 8; bb++) acc[jj][bb] = 0ull;

#pragma unroll
    for (int jj = 0; jj < 4; jj++) {
        ulonglong2 kp = *(const ulonglong2*)&key_pos[((size_t)(j0 + jj) * NH + h) * NDK + lane * 4];
#pragma unroll
        for (int bb = 0; bb < 8; bb++) {
            ffma2(acc[jj][bb], qb[bb][0], kp.x);
            ffma2(acc[jj][bb], qb[bb][1], kp.y);
        }
    }
    float v[32];
#pragma unroll
    for (int jj = 0; jj < 4; jj++)
#pragma unroll
        for (int bb = 0; bb < 8; bb++) {
            float2 p = unpack2(acc[jj][bb]);
            v[jj * 8 + bb] = p.x + p.y;
        }
    int n = 32;
#pragma unroll
    for (int half = 16; half >= 1; half >>= 1) {
        int m = n >> 1;
        bool upper = (lane & half) != 0;
#pragma unroll
        for (int i = 0; i < 16; i++) {
            if (i >= m) break;
            float send = upper ? v[i] : v[i + m];
            float recv = __shfl_xor_sync(0xffffffffu, send, half);
            v[i] = (upper ? v[i + m] : v[i]) + recv;
        }
        n = m;
    }
    int jj = lane >> 3, bb = lane & 7;
    g_pos[(j0 + jj) * 128 + bb * 16 + h] = v[0] * SCALE;
}

// ---------------- K5: softmax stats per (b,h) over scores+pos ----------------
__global__ void k_softmax() {
    int bh = blockIdx.x;
    int tid = threadIdx.x;
    __shared__ float red[256];
    float mx = -1e30f;
    for (int j = tid; j < NS; j += 256)
        mx = fmaxf(mx, g_scores[j * (NB * NH) + bh] + g_pos[j * (NB * NH) + bh]);
    red[tid] = mx; __syncthreads();
    for (int s = 128; s; s >>= 1) { if (tid < s) red[tid] = fmaxf(red[tid], red[tid + s]); __syncthreads(); }
    float m = red[0]; __syncthreads();
    float sum = 0.f;
    for (int j = tid; j < NS; j += 256)
        sum += __expf(g_scores[j * (NB * NH) + bh] + g_pos[j * (NB * NH) + bh] - m);
    red[tid] = sum; __syncthreads();
    for (int s = 128; s; s >>= 1) { if (tid < s) red[tid] += red[tid + s]; __syncthreads(); }
    if (tid == 0) { g_m[bh] = m; g_linv[bh] = 1.0f / red[0]; }
}

// ---------------- K6: value pass — f32x2, 2 e-columns per thread ----------------
__global__ __launch_bounds__(256) void k_value(const float* __restrict__ value) {
    const int tid = threadIdx.x;
    const int b = blockIdx.y, jc = blockIdx.z;
    const int e = blockIdx.x * 512 + tid;       // columns e and e+256
    const int j0 = jc * 256;
    __shared__ __align__(16) float ws[256 * 16];
    __shared__ float ms[16], ls[16];
    if (tid < 16) { ms[tid] = g_m[b * 16 + tid]; ls[tid] = g_linv[b * 16 + tid]; }
    __syncthreads();
    for (int idx = tid; idx < 4096; idx += 256) {
        int jl = idx >> 4, h = idx & 15;
        int gi = (j0 + jl) * 128 + b * 16 + h;
        ws[idx] = __expf(g_scores[gi] + g_pos[gi] - ms[h]) * ls[h];
    }
    __syncthreads();

    u64 accA[8], accB[8];
#pragma unroll
    for (int p = 0; p < 8; p++) { accA[p] = 0ull; accB[p] = 0ull; }

    const float* vp = value + ((size_t)j0 * NB + b) * ND + e;
#pragma unroll 4
    for (int jl = 0; jl < 256; jl++) {
        float c0 = vp[0];
        float c1 = vp[256];
        vp += (size_t)NB * ND;
        u64 p0 = pack2(c0, c0), p1 = pack2(c1, c1);
        const ulonglong2* wr = (const ulonglong2*)(ws + jl * 16);
        ulonglong2 wA = wr[0], wB = wr[1];
        ffma2(accA[0], wA.x, p0); ffma2(accB[0], wA.x, p1);
        ffma2(accA[1], wA.y, p0); ffma2(accB[1], wA.y, p1);
        ffma2(accA[2], wB.x, p0); ffma2(accB[2], wB.x, p1);
        ffma2(accA[3], wB.y, p0); ffma2(accB[3], wB.y, p1);
        ulonglong2 wC = wr[2], wD = wr[3];
        ffma2(accA[4], wC.x, p0); ffma2(accB[4], wC.x, p1);
        ffma2(accA[5], wC.y, p0); ffma2(accB[5], wC.y, p1);
        ffma2(accA[6], wD.x, p0); ffma2(accB[6], wD.x, p1);
        ffma2(accA[7], wD.y, p0); ffma2(accB[7], wD.y, p1);
    }
    int rb = (jc * 8 + b) * 16;
#pragma unroll
    for (int p = 0; p < 8; p++) {
        float2 a = unpack2(accA[p]);
        float2 c = unpack2(accB[p]);
        g_upart[(rb + 2 * p    ) * ND + e]       = a.x;
        g_upart[(rb + 2 * p + 1) * ND + e]       = a.y;
        g_upart[(rb + 2 * p    ) * ND + e + 256] = c.x;
        g_upart[(rb + 2 * p + 1) * ND + e + 256] = c.y;
    }
}

// ---------------- K7: x partials = u @ Wv (per head), e-split 16, MLP 8/16 ----------------
__global__ __launch_bounds__(128) void k_projv(const float* __restrict__ Wv) {
    int tid = threadIdx.x;   // 128 (= d)
    int h = blockIdx.y;
    int e0 = blockIdx.x * 128;
    __shared__ float us[8][128];
    for (int idx = tid; idx < 1024; idx += 128) {
        int bb = idx >> 7, el = idx & 127;
        float s = 0.f;
#pragma unroll
        for (int jc = 0; jc < 16; jc++)
            s += g_upart[((jc * 8 + bb) * 16 + h) * ND + e0 + el];
        us[bb][el] = s;
    }
    __syncthreads();
    float acc[8] = {0.f,0.f,0.f,0.f,0.f,0.f,0.f,0.f};
    for (int el = 0; el < 128; el += 8) {
        float w[8];
#pragma unroll
        for (int k2 = 0; k2 < 8; k2++)
            w[k2] = Wv[(e0 + el + k2) * ND + h * NDK + tid];
#pragma unroll
        for (int k2 = 0; k2 < 8; k2++)
#pragma unroll
            for (int bb = 0; bb < 8; bb++) acc[bb] = fmaf(w[k2], us[bb][el + k2], acc[bb]);
    }
#pragma unroll
    for (int bb = 0; bb < 8; bb++)
        g_xpart[(blockIdx.x * 8 + bb) * ND + h * NDK + tid] = acc[bb];
}

__global__ void k_xred(const float* __restrict__ bv) {
    int i = blockIdx.x * 256 + threadIdx.x;
    int c = i & (ND - 1), b = i >> 11;
    float s = bv[c];
#pragma unroll
    for (int ec = 0; ec < 16; ec++) s += g_xpart[(ec * 8 + b) * ND + c];
    g_x[i] = s;
}

// ---------------- K8: out partials = x @ Wo, g-split 16, MLP 8 ----------------
__global__ __launch_bounds__(256) void k_out(const float* __restrict__ Wo) {
    int tid = threadIdx.x;
    int f = blockIdx.x * 256 + tid;
    int g0 = blockIdx.y * 128;
    __shared__ float xs[8][128];
    for (int idx = tid; idx < 1024; idx += 256)
        xs[idx >> 7][idx & 127] = g_x[(idx >> 7) * ND + g0 + (idx & 127)];
    __syncthreads();
    float acc[8] = {0.f,0.f,0.f,0.f,0.f,0.f,0.f,0.f};
    for (int g = 0; g < 128; g += 8) {
        float w[8];
#pragma unroll
        for (int k2 = 0; k2 < 8; k2++) w[k2] = Wo[(g0 + g + k2) * ND + f];
#pragma unroll
        for (int k2 = 0; k2 < 8; k2++)
#pragma unroll
            for (int b = 0; b < 8; b++) acc[b] = fmaf(w[k2], xs[b][g + k2], acc[b]);
    }
#pragma unroll
    for (int b = 0; b < 8; b++) g_opart[(blockIdx.y * 8 + b) * ND + f] = acc[b];
}

__global__ void k_ored(const float* __restrict__ bo, float* __restrict__ out) {
    int i = blockIdx.x * 256 + threadIdx.x;
    int c = i & (ND - 1), b = i >> 11;
    float s = bo[c];
#pragma unroll
    for (int gc = 0; gc < 16; gc++) s += g_opart[(gc * 8 + b) * ND + c];
    out[i] = s;
}

extern "C" void kernel_launch(void* const* d_in, const int* in_sizes, int n_in,
                              void* d_out, int out_size) {
    const float* query   = (const float*)d_in[0];
    const float* key     = (const float*)d_in[1];
    const float* value   = (const float*)d_in[2];
    const float* Wq      = (const float*)d_in[3];
    const float* Wk      = (const float*)d_in[4];
    const float* Wv      = (const float*)d_in[5];
    const float* bv      = (const float*)d_in[6];
    const float* Wo      = (const float*)d_in[7];
    const float* bo      = (const float*)d_in[8];
    const float* key_pos = (const float*)d_in[9];
    const float* q_bias  = (const float*)d_in[10];
    float* out = (float*)d_out;

    // Order matters: k_scores is launch idx 3 so the profiler's fixed slot lands on it.
    k_qbp    <<<dim3(8, 16),     256>>>(query, Wq);
    k_qb     <<<64,              256>>>(q_bias);
    k_A      <<<dim3(16, 16),    128>>>(Wk);
    k_scores <<<dim3(128, 8),    256>>>(key);
    k_pos    <<<dim3(1024, 2),   256>>>(key_pos);
    k_softmax<<<128,             256>>>();
    k_value  <<<dim3(4, 8, 16),  256>>>(value);
    k_projv  <<<dim3(16, 16),    128>>>(Wv);
    k_xred   <<<64,              256>>>(bv);
    k_out    <<<dim3(8, 16),     256>>>(Wo);
    k_ored   <<<64,              256>>>(bo, out);
}

// round 6
// speedup vs baseline: 1.2528x; 1.0535x over previous
#include <cuda_runtime.h>
#include <math.h>

// Shapes
#define NB 8
#define NS 4096
#define ND 2048
#define NH 16
#define NDK 128
#define SCALE 0.08838834764831845f   // 1/sqrt(128)

typedef unsigned long long u64;

__device__ __forceinline__ void ffma2(u64& d, u64 a, u64 b) {
    asm("fma.rn.f32x2 %0, %1, %2, %0;" : "+l"(d) : "l"(a), "l"(b));
}
__device__ __forceinline__ u64 pack2(float x, float y) {
    u64 r; asm("mov.b64 %0, {%1, %2};" : "=l"(r) : "f"(x), "f"(y)); return r;
}
__device__ __forceinline__ float2 unpack2(u64 v) {
    float2 r; asm("mov.b64 {%0, %1}, %2;" : "=f"(r.x), "=f"(r.y) : "l"(v)); return r;
}

// -------- device scratch (no allocations allowed) --------
__device__ __align__(16) float g_qbp[16 * NB * ND];
__device__ __align__(16) float g_qb[NB * ND];                 // [b][h*128+d]
__device__ __align__(16) float g_A[NB * NH * ND];             // A[b][h][e]
__device__ __align__(16) float g_scores[NS * NB * NH];        // SCALE*(A.key), then += pos
__device__ float g_m[NB * NH];
__device__ float g_linv[NB * NH];
__device__ __align__(16) float g_upart[32 * NB * NH * ND];    // [jc(32)][b][h][e]
__device__ __align__(16) float g_xpart[16 * NB * ND];
__device__ __align__(16) float g_x[NB * ND];
__device__ __align__(16) float g_opart[16 * NB * ND];

// ---------------- K1: qb partials: (query @ Wq), g-split 16, MLP 8 ----------------
__global__ __launch_bounds__(256) void k_qbp(const float* __restrict__ query,
                                             const float* __restrict__ Wq) {
    int tid = threadIdx.x;
    int c   = blockIdx.x * 256 + tid;
    int g0  = blockIdx.y * 128;
    __shared__ float qs[8][128];
    for (int idx = tid; idx < 1024; idx += 256)
        qs[idx >> 7][idx & 127] = query[(idx >> 7) * ND + g0 + (idx & 127)];
    __syncthreads();
    float acc[8] = {0.f,0.f,0.f,0.f,0.f,0.f,0.f,0.f};
    for (int g = 0; g < 128; g += 8) {
        float w[8];
#pragma unroll
        for (int k2 = 0; k2 < 8; k2++) w[k2] = Wq[(g0 + g + k2) * ND + c];
#pragma unroll
        for (int k2 = 0; k2 < 8; k2++)
#pragma unroll
            for (int b = 0; b < 8; b++) acc[b] = fmaf(w[k2], qs[b][g + k2], acc[b]);
    }
#pragma unroll
    for (int b = 0; b < 8; b++) g_qbp[(blockIdx.y * 8 + b) * ND + c] = acc[b];
}

__global__ void k_qb(const float* __restrict__ q_bias) {
    int i = blockIdx.x * 256 + threadIdx.x;
    int c = i & (ND - 1);
    int b = i >> 11;
    float s = q_bias[c];
#pragma unroll
    for (int gc = 0; gc < 16; gc++) s += g_qbp[(gc * 8 + b) * ND + c];
    g_qb[i] = s;
}

// ---------------- K2: A[b][h][e] = sum_d Wk[e][h*128+d] * qb[b][h*128+d] ----------------
__global__ void k_A(const float* __restrict__ Wk) {
    int tid = threadIdx.x;           // 128
    int h   = blockIdx.y;
    int e0  = blockIdx.x * 128;
    __shared__ float qbs[8][128];
    __shared__ float wks[128][65];
    for (int idx = tid; idx < 1024; idx += 128)
        qbs[idx >> 7][idx & 127] = g_qb[(idx >> 7) * ND + h * NDK + (idx & 127)];
    float acc[8] = {0.f,0.f,0.f,0.f,0.f,0.f,0.f,0.f};
    for (int st = 0; st < 2; st++) {
        __syncthreads();
        for (int idx = tid; idx < 128 * 64; idx += 128) {
            int r = idx >> 6, cc = idx & 63;
            wks[r][cc] = Wk[(e0 + r) * ND + h * NDK + st * 64 + cc];
        }
        __syncthreads();
#pragma unroll 8
        for (int d = 0; d < 64; d++) {
            float w = wks[tid][d];
#pragma unroll
            for (int b = 0; b < 8; b++) acc[b] = fmaf(w, qbs[b][st * 64 + d], acc[b]);
        }
    }
    int e = e0 + tid;
#pragma unroll
    for (int b = 0; b < 8; b++) g_A[(b * NH + h) * ND + e] = acc[b];
}

// ---------------- K4: score pass — 16 warps: (j-grp of 4) x (h-half of 8) ----------------
__global__ __launch_bounds__(512, 1) void k_scores(const float* __restrict__ key) {
    const int b = blockIdx.y;
    const int warp = threadIdx.x >> 5, lane = threadIdx.x & 31;
    const int jgrp  = warp >> 1;
    const int hbase = (warp & 1) * 8;
    const int j0w = blockIdx.x * 32 + jgrp * 4;
    __shared__ __align__(16) float As[16 * 2048];
    for (int idx = threadIdx.x; idx < 8192; idx += 512)
        ((float4*)As)[idx] = ((const float4*)(g_A + (size_t)b * NH * ND))[idx];
    __syncthreads();

    u64 acc[8][4];
#pragma unroll
    for (int hh = 0; hh < 8; hh++)
#pragma unroll
        for (int jj = 0; jj < 4; jj++) acc[hh][jj] = 0ull;

    const float* kbase = key + ((size_t)j0w * NB + b) * ND + lane * 4;
    const float* apb   = As + hbase * 2048 + lane * 4;
#pragma unroll 2
    for (int e0 = 0; e0 < 2048; e0 += 128) {
        ulonglong2 kv[4];
#pragma unroll
        for (int jj = 0; jj < 4; jj++)
            kv[jj] = *(const ulonglong2*)(kbase + (size_t)jj * (NB * ND) + e0);
        const float* ap = apb + e0;
#pragma unroll
        for (int hh = 0; hh < 8; hh++) {
            ulonglong2 a = *(const ulonglong2*)(ap + hh * 2048);
#pragma unroll
            for (int jj = 0; jj < 4; jj++) {
                ffma2(acc[hh][jj], a.x, kv[jj].x);
                ffma2(acc[hh][jj], a.y, kv[jj].y);
            }
        }
    }
    float v[32];
#pragma unroll
    for (int hh = 0; hh < 8; hh++)
#pragma unroll
        for (int jj = 0; jj < 4; jj++) {
            float2 p = unpack2(acc[hh][jj]);
            v[jj * 8 + hh] = p.x + p.y;
        }
    int n = 32;
#pragma unroll
    for (int half = 16; half >= 1; half >>= 1) {
        int m = n >> 1;
        bool upper = (lane & half) != 0;
#pragma unroll
        for (int i = 0; i < 16; i++) {
            if (i >= m) break;
            float send = upper ? v[i] : v[i + m];
            float recv = __shfl_xor_sync(0xffffffffu, send, half);
            v[i] = (upper ? v[i + m] : v[i]) + recv;
        }
        n = m;
    }
    int jj = lane >> 3, hh = lane & 7;
    g_scores[(j0w + jj) * 128 + b * 16 + hbase + hh] = v[0] * SCALE;
}

// ---------------- K3: g_scores += SCALE * (qb[b][h] . key_pos[j][h]) ----------------
__global__ __launch_bounds__(256) void k_pos(const float* __restrict__ key_pos) {
    const int warp = threadIdx.x >> 5, lane = threadIdx.x & 31;
    const int h  = blockIdx.y * 8 + warp;
    const int j0 = blockIdx.x * 4;

    u64 qb[8][2];
#pragma unroll
    for (int bb = 0; bb < 8; bb++) {
        ulonglong2 q = *(const ulonglong2*)&g_qb[bb * ND + h * NDK + lane * 4];
        qb[bb][0] = q.x; qb[bb][1] = q.y;
    }
    u64 acc[4][8];
#pragma unroll
    for (int jj = 0; jj < 4; jj++)
#pragma unroll
        for (int bb = 0; bb < 8; bb++) acc[jj][bb] = 0ull;

#pragma unroll
    for (int jj = 0; jj < 4; jj++) {
        ulonglong2 kp = *(const ulonglong2*)&key_pos[((size_t)(j0 + jj) * NH + h) * NDK + lane * 4];
#pragma unroll
        for (int bb = 0; bb < 8; bb++) {
            ffma2(acc[jj][bb], qb[bb][0], kp.x);
            ffma2(acc[jj][bb], qb[bb][1], kp.y);
        }
    }
    float v[32];
#pragma unroll
    for (int jj = 0; jj < 4; jj++)
#pragma unroll
        for (int bb = 0; bb < 8; bb++) {
            float2 p = unpack2(acc[jj][bb]);
            v[jj * 8 + bb] = p.x + p.y;
        }
    int n = 32;
#pragma unroll
    for (int half = 16; half >= 1; half >>= 1) {
        int m = n >> 1;
        bool upper = (lane & half) != 0;
#pragma unroll
        for (int i = 0; i < 16; i++) {
            if (i >= m) break;
            float send = upper ? v[i] : v[i + m];
            float recv = __shfl_xor_sync(0xffffffffu, send, half);
            v[i] = (upper ? v[i + m] : v[i]) + recv;
        }
        n = m;
    }
    int jj = lane >> 3, bb = lane & 7;
    int gi = (j0 + jj) * 128 + bb * 16 + h;
    g_scores[gi] = g_scores[gi] + v[0] * SCALE;   // accumulate pos in place
}

// ---------------- K5: softmax stats per (b,h) ----------------
__global__ void k_softmax() {
    int bh = blockIdx.x;
    int tid = threadIdx.x;
    __shared__ float red[256];
    float mx = -1e30f;
    for (int j = tid; j < NS; j += 256)
        mx = fmaxf(mx, g_scores[j * (NB * NH) + bh]);
    red[tid] = mx; __syncthreads();
    for (int s = 128; s; s >>= 1) { if (tid < s) red[tid] = fmaxf(red[tid], red[tid + s]); __syncthreads(); }
    float m = red[0]; __syncthreads();
    float sum = 0.f;
    for (int j = tid; j < NS; j += 256)
        sum += __expf(g_scores[j * (NB * NH) + bh] - m);
    red[tid] = sum; __syncthreads();
    for (int s = 128; s; s >>= 1) { if (tid < s) red[tid] += red[tid + s]; __syncthreads(); }
    if (tid == 0) { g_m[bh] = m; g_linv[bh] = 1.0f / red[0]; }
}

// ---------------- K6: value pass — float4, 4 e-cols/thread, (w,w) u64 smem ----------------
__global__ __launch_bounds__(256) void k_value(const float* __restrict__ value) {
    const int tid = threadIdx.x;
    const int b = blockIdx.y, jc = blockIdx.z;
    const int e = blockIdx.x * 1024 + tid * 4;
    const int j0 = jc * 128;
    __shared__ __align__(16) u64 ws2[128 * 16];
    __shared__ float ms[16], ls[16];
    if (tid < 16) { ms[tid] = g_m[b * 16 + tid]; ls[tid] = g_linv[b * 16 + tid]; }
    __syncthreads();
    for (int idx = tid; idx < 2048; idx += 256) {
        int jl = idx >> 4, h = idx & 15;
        float w = __expf(g_scores[(j0 + jl) * 128 + b * 16 + h] - ms[h]) * ls[h];
        ws2[idx] = pack2(w, w);
    }
    __syncthreads();

    u64 acc[16][2];
#pragma unroll
    for (int h = 0; h < 16; h++) { acc[h][0] = 0ull; acc[h][1] = 0ull; }

    const float* vp = value + ((size_t)j0 * NB + b) * ND + e;
#pragma unroll 4
    for (int jl = 0; jl < 128; jl++) {
        ulonglong2 v2 = *(const ulonglong2*)(vp + (size_t)jl * (NB * ND));
        const ulonglong2* wr = (const ulonglong2*)(ws2 + jl * 16);
#pragma unroll
        for (int h2 = 0; h2 < 8; h2++) {
            ulonglong2 wp = wr[h2];
            ffma2(acc[2 * h2    ][0], wp.x, v2.x);
            ffma2(acc[2 * h2    ][1], wp.x, v2.y);
            ffma2(acc[2 * h2 + 1][0], wp.y, v2.x);
            ffma2(acc[2 * h2 + 1][1], wp.y, v2.y);
        }
    }
    int rb = (jc * 8 + b) * 16;
#pragma unroll
    for (int h = 0; h < 16; h++) {
        ulonglong2 o; o.x = acc[h][0]; o.y = acc[h][1];
        *(ulonglong2*)&g_upart[(size_t)(rb + h) * ND + e] = o;
    }
}

// ---------------- K7: x partials = u @ Wv (per head), e-split 16 ----------------
__global__ __launch_bounds__(128) void k_projv(const float* __restrict__ Wv) {
    int tid = threadIdx.x;   // 128 (= d)
    int h = blockIdx.y;
    int e0 = blockIdx.x * 128;
    __shared__ float us[8][128];
    for (int idx = tid; idx < 1024; idx += 128) {
        int bb = idx >> 7, el = idx & 127;
        float s = 0.f;
#pragma unroll
        for (int jc = 0; jc < 32; jc++)
            s += g_upart[(size_t)((jc * 8 + bb) * 16 + h) * ND + e0 + el];
        us[bb][el] = s;
    }
    __syncthreads();
    float acc[8] = {0.f,0.f,0.f,0.f,0.f,0.f,0.f,0.f};
    for (int el = 0; el < 128; el += 8) {
        float w[8];
#pragma unroll
        for (int k2 = 0; k2 < 8; k2++)
            w[k2] = Wv[(e0 + el + k2) * ND + h * NDK + tid];
#pragma unroll
        for (int k2 = 0; k2 < 8; k2++)
#pragma unroll
            for (int bb = 0; bb < 8; bb++) acc[bb] = fmaf(w[k2], us[bb][el + k2], acc[bb]);
    }
#pragma unroll
    for (int bb = 0; bb < 8; bb++)
        g_xpart[(blockIdx.x * 8 + bb) * ND + h * NDK + tid] = acc[bb];
}

__global__ void k_xred(const float* __restrict__ bv) {
    int i = blockIdx.x * 256 + threadIdx.x;
    int c = i & (ND - 1), b = i >> 11;
    float s = bv[c];
#pragma unroll
    for (int ec = 0; ec < 16; ec++) s += g_xpart[(ec * 8 + b) * ND + c];
    g_x[i] = s;
}

// ---------------- K8: out partials = x @ Wo, g-split 16, MLP 8 ----------------
__global__ __launch_bounds__(256) void k_out(const float* __restrict__ Wo) {
    int tid = threadIdx.x;
    int f = blockIdx.x * 256 + tid;
    int g0 = blockIdx.y * 128;
    __shared__ float xs[8][128];
    for (int idx = tid; idx < 1024; idx += 256)
        xs[idx >> 7][idx & 127] = g_x[(idx >> 7) * ND + g0 + (idx & 127)];
    __syncthreads();
    float acc[8] = {0.f,0.f,0.f,0.f,0.f,0.f,0.f,0.f};
    for (int g = 0; g < 128; g += 8) {
        float w[8];
#pragma unroll
        for (int k2 = 0; k2 < 8; k2++) w[k2] = Wo[(g0 + g + k2) * ND + f];
#pragma unroll
        for (int k2 = 0; k2 < 8; k2++)
#pragma unroll
            for (int b = 0; b < 8; b++) acc[b] = fmaf(w[k2], xs[b][g + k2], acc[b]);
    }
#pragma unroll
    for (int b = 0; b < 8; b++) g_opart[(blockIdx.y * 8 + b) * ND + f] = acc[b];
}

__global__ void k_ored(const float* __restrict__ bo, float* __restrict__ out) {
    int i = blockIdx.x * 256 + threadIdx.x;
    int c = i & (ND - 1), b = i >> 11;
    float s = bo[c];
#pragma unroll
    for (int gc = 0; gc < 16; gc++) s += g_opart[(gc * 8 + b) * ND + c];
    out[i] = s;
}

extern "C" void kernel_launch(void* const* d_in, const int* in_sizes, int n_in,
                              void* d_out, int out_size) {
    const float* query   = (const float*)d_in[0];
    const float* key     = (const float*)d_in[1];
    const float* value   = (const float*)d_in[2];
    const float* Wq      = (const float*)d_in[3];
    const float* Wk      = (const float*)d_in[4];
    const float* Wv      = (const float*)d_in[5];
    const float* bv      = (const float*)d_in[6];
    const float* Wo      = (const float*)d_in[7];
    const float* bo      = (const float*)d_in[8];
    const float* key_pos = (const float*)d_in[9];
    const float* q_bias  = (const float*)d_in[10];
    float* out = (float*)d_out;

    // k_scores kept at launch idx 3 so the profiler's fixed slot lands on it.
    k_qbp    <<<dim3(8, 16),     256>>>(query, Wq);
    k_qb     <<<64,              256>>>(q_bias);
    k_A      <<<dim3(16, 16),    128>>>(Wk);
    k_scores <<<dim3(128, 8),    512>>>(key);
    k_pos    <<<dim3(1024, 2),   256>>>(key_pos);
    k_softmax<<<128,             256>>>();
    k_value  <<<dim3(2, 8, 32),  256>>>(value);
    k_projv  <<<dim3(16, 16),    128>>>(Wv);
    k_xred   <<<64,              256>>>(bv);
    k_out    <<<dim3(8, 16),     256>>>(Wo);
    k_ored   <<<64,              256>>>(bo, out);
}